// round 1
// baseline (speedup 1.0000x reference)
#include <cuda_runtime.h>
#include <cstdint>

// Problem constants (fixed by setup_inputs):
//   B=16, H_out=W_out=512 -> N = 262144 = 2^18
//   source: [B, 640, 640, 3] f32
//   idx:    [B, 2, N] f32
//   out:    [B, 512, 512, 3] f32
#define B_     16
#define N_     262144      // 2^18
#define N_LOG2 18
#define HS_    640
#define WS_    640
#define C_     3
#define PIX_PER_THREAD 4

__global__ __launch_bounds__(256)
void nn_gather_kernel(const float* __restrict__ idx,
                      const float* __restrict__ src,
                      float* __restrict__ out)
{
    const int64_t tid = (int64_t)blockIdx.x * blockDim.x + threadIdx.x;
    const int64_t p0  = tid * PIX_PER_THREAD;          // global pixel index
    const int     b   = (int)(p0 >> N_LOG2);
    const int     n   = (int)(p0 & (N_ - 1));          // multiple of 4 -> 16B aligned

    const float* idx_b = idx + (int64_t)b * 2 * N_;
    const float4 rv = *reinterpret_cast<const float4*>(idx_b + n);        // rows
    const float4 cv = *reinterpret_cast<const float4*>(idx_b + N_ + n);   // cols

    const float* src_b = src + (int64_t)b * (HS_ * WS_ * C_);

    float rr[4] = {rv.x, rv.y, rv.z, rv.w};
    float cc[4] = {cv.x, cv.y, cv.z, cv.w};

    float o[12];
    #pragma unroll
    for (int k = 0; k < 4; ++k) {
        // trunc(x + 0.5) toward zero, then int cast  == __float2int_rz(x+0.5f)
        const int ir = __float2int_rz(rr[k] + 0.5f);
        const int ic = __float2int_rz(cc[k] + 0.5f);
        const bool valid = ((unsigned)ir < (unsigned)HS_) &&
                           ((unsigned)ic < (unsigned)WS_);
        const int irc = min(max(ir, 0), HS_ - 1);
        const int icc = min(max(ic, 0), WS_ - 1);
        const float* p = src_b + ((int64_t)irc * WS_ + icc) * C_;
        const float v0 = __ldg(p + 0);
        const float v1 = __ldg(p + 1);
        const float v2 = __ldg(p + 2);
        o[3 * k + 0] = valid ? v0 : 0.0f;
        o[3 * k + 1] = valid ? v1 : 0.0f;
        o[3 * k + 2] = valid ? v2 : 0.0f;
    }

    // 4 pixels * 3ch = 12 floats = 48B, starting at byte offset 48*tid -> 16B aligned
    float4* op = reinterpret_cast<float4*>(out + p0 * C_);
    op[0] = make_float4(o[0], o[1],  o[2],  o[3]);
    op[1] = make_float4(o[4], o[5],  o[6],  o[7]);
    op[2] = make_float4(o[8], o[9],  o[10], o[11]);
}

extern "C" void kernel_launch(void* const* d_in, const int* in_sizes, int n_in,
                              void* d_out, int out_size)
{
    const float* idx = (const float*)d_in[0];   // [B, 2, N] f32
    const float* src = (const float*)d_in[1];   // [B, 640, 640, 3] f32
    float* out = (float*)d_out;                 // [B, 512, 512, 3] f32

    const int64_t total_pixels  = (int64_t)B_ * N_;                 // 4,194,304
    const int64_t total_threads = total_pixels / PIX_PER_THREAD;    // 1,048,576
    const int threads = 256;
    const int blocks  = (int)(total_threads / threads);             // 4096

    nn_gather_kernel<<<blocks, threads>>>(idx, src, out);
}

// round 2
// speedup vs baseline: 1.0839x; 1.0839x over previous
#include <cuda_runtime.h>
#include <cstdint>

// Problem constants (fixed by setup_inputs):
//   B=16, H_out=W_out=512 -> N = 262144 = 2^18
//   source: [B, 640, 640, 3] f32
//   idx:    [B, 2, N] f32
//   out:    [B, 512, 512, 3] f32
#define B_     16
#define N_     262144      // 2^18
#define N_LOG2 18
#define HS_    640
#define WS_    640
#define C_     3
#define PIX_PER_THREAD 4

__global__ __launch_bounds__(256)
void nn_gather_kernel(const float* __restrict__ idx,
                      const float* __restrict__ src,
                      float* __restrict__ out)
{
    const int64_t tid = (int64_t)blockIdx.x * blockDim.x + threadIdx.x;
    const int64_t p0  = tid * PIX_PER_THREAD;          // global pixel index
    const int     b   = (int)(p0 >> N_LOG2);
    const int     n   = (int)(p0 & (N_ - 1));          // multiple of 4 -> 16B aligned

    const float* idx_b = idx + (int64_t)b * 2 * N_;
    const float4 rv = *reinterpret_cast<const float4*>(idx_b + n);        // rows
    const float4 cv = *reinterpret_cast<const float4*>(idx_b + N_ + n);   // cols

    // per-image base, 16B aligned (1228800 floats per image)
    const float4* src4 = reinterpret_cast<const float4*>(src + (int64_t)b * (HS_ * WS_ * C_));

    float rr[4] = {rv.x, rv.y, rv.z, rv.w};
    float cc[4] = {cv.x, cv.y, cv.z, cv.w};

    float o[12];
    #pragma unroll
    for (int k = 0; k < 4; ++k) {
        // trunc(x + 0.5) toward zero == __float2int_rz(x + 0.5f)
        const int ir = __float2int_rz(rr[k] + 0.5f);
        const int ic = __float2int_rz(cc[k] + 0.5f);
        const bool valid = ((unsigned)ir < (unsigned)HS_) &&
                           ((unsigned)ic < (unsigned)WS_);
        const int irc = min(max(ir, 0), HS_ - 1);
        const int icc = min(max(ic, 0), WS_ - 1);

        const int off   = (irc * WS_ + icc) * C_;   // float offset within image, 4B-aligned
        const int base4 = off >> 2;                  // aligned float4 index
        const int rem   = off & 3;                   // 0..3

        // One aligned 16B load always; second 16B load only when the 12B pixel
        // straddles the 16B boundary (rem >= 2). Proven in-bounds for all pixels.
        const float4 q0 = __ldg(src4 + base4);
        float4 q1 = make_float4(0.0f, 0.0f, 0.0f, 0.0f);
        if (rem >= 2) q1 = __ldg(src4 + base4 + 1);

        // channel select: pixel floats are at base4*4 + rem + {0,1,2}
        const bool e0 = (rem == 0), e1 = (rem == 1), e2 = (rem == 2);
        float v0 = e0 ? q0.x : e1 ? q0.y : e2 ? q0.z : q0.w;
        float v1 = e0 ? q0.y : e1 ? q0.z : e2 ? q0.w : q1.x;
        float v2 = e0 ? q0.z : e1 ? q0.w : e2 ? q1.x : q1.y;

        o[3 * k + 0] = valid ? v0 : 0.0f;
        o[3 * k + 1] = valid ? v1 : 0.0f;
        o[3 * k + 2] = valid ? v2 : 0.0f;
    }

    // 4 pixels * 3ch = 12 floats = 48B at byte offset 48*tid -> 16B aligned
    float4* op = reinterpret_cast<float4*>(out + p0 * C_);
    op[0] = make_float4(o[0], o[1],  o[2],  o[3]);
    op[1] = make_float4(o[4], o[5],  o[6],  o[7]);
    op[2] = make_float4(o[8], o[9],  o[10], o[11]);
}

extern "C" void kernel_launch(void* const* d_in, const int* in_sizes, int n_in,
                              void* d_out, int out_size)
{
    const float* idx = (const float*)d_in[0];   // [B, 2, N] f32
    const float* src = (const float*)d_in[1];   // [B, 640, 640, 3] f32
    float* out = (float*)d_out;                 // [B, 512, 512, 3] f32

    const int64_t total_pixels  = (int64_t)B_ * N_;                 // 4,194,304
    const int64_t total_threads = total_pixels / PIX_PER_THREAD;    // 1,048,576
    const int threads = 256;
    const int blocks  = (int)(total_threads / threads);             // 4096

    nn_gather_kernel<<<blocks, threads>>>(idx, src, out);
}